// round 3
// baseline (speedup 1.0000x reference)
#include <cuda_runtime.h>

#define NA 8192
#define NN 65536
#define NE 262144
#define DD 128
#define GN_EPS 1e-5f
#define TILE 64
#define AST 132      // activation row stride (floats)
#define CST 132      // gemm-output row stride
#define INST 388     // ctx0-input row stride (3*128 padded)
#define NTH 256

// scratch (device globals: allocation-free rule)
__device__ __align__(16) float g_q[NA * DD];
__device__ __align__(16) float g_a[NA * DD];
__device__ __align__(16) float g_actors[NA * DD];

// ---------- packed f32x2 helpers ----------
__device__ __forceinline__ void ffma2(unsigned long long& acc, unsigned long long w,
                                      unsigned long long a) {
    asm volatile("fma.rn.f32x2 %0, %1, %2, %0;" : "+l"(acc) : "l"(w), "l"(a));
}
__device__ __forceinline__ unsigned long long pack2(float x) {
    unsigned long long r;
    asm("mov.b64 %0, {%1, %1};" : "=l"(r) : "f"(x));
    return r;
}
__device__ __forceinline__ float2 unpack2(unsigned long long v) {
    float2 r;
    asm("mov.b64 {%0, %1}, %2;" : "=f"(r.x), "=f"(r.y) : "l"(v));
    return r;
}

// ---------- CTA-tiled GEMM:  C[64][128] = Act[64][K] * W[128][K]^T ----------
// thread layout: toc = t&31 (4 output channels, as 2 f32x2 pairs), teg = t>>5 (8 edges)
// W staged k-major in smem (sW[kk][oc]) in 16-wide k chunks, prefetched to regs.
__device__ void cta_gemm(const float* __restrict__ W, int K,
                         const float* sAct, int actStride,
                         float* sC, float* sW, int t) {
    const int toc = t & 31;
    const int teg = t >> 5;
    unsigned long long acc[8][2];
#pragma unroll
    for (int i = 0; i < 8; i++) { acc[i][0] = 0ull; acc[i][1] = 0ull; }

    const int nchunk = K >> 4;
    float4 wreg[2];
    {
        int i0 = t, i1 = t + NTH;
        wreg[0] = *(const float4*)(W + (i0 >> 2) * K + (i0 & 3) * 4);
        wreg[1] = *(const float4*)(W + (i1 >> 2) * K + (i1 & 3) * 4);
    }
    for (int c = 0; c < nchunk; c++) {
        __syncthreads();  // previous chunk fully consumed
#pragma unroll
        for (int r = 0; r < 2; r++) {
            int idx = t + r * NTH;
            int oc = idx >> 2, kq = idx & 3;
            sW[(kq * 4 + 0) * 128 + oc] = wreg[r].x;
            sW[(kq * 4 + 1) * 128 + oc] = wreg[r].y;
            sW[(kq * 4 + 2) * 128 + oc] = wreg[r].z;
            sW[(kq * 4 + 3) * 128 + oc] = wreg[r].w;
        }
        __syncthreads();
        if (c + 1 < nchunk) {
            int k0n = (c + 1) << 4;
#pragma unroll
            for (int r = 0; r < 2; r++) {
                int idx = t + r * NTH;
                wreg[r] = *(const float4*)(W + (idx >> 2) * K + k0n + (idx & 3) * 4);
            }
        }
        const int k0 = c << 4;
#pragma unroll
        for (int kq = 0; kq < 4; kq++) {
            float a[8][4];
#pragma unroll
            for (int i = 0; i < 8; i++)
                *(float4*)(&a[i][0]) =
                    *(const float4*)(sAct + (teg * 8 + i) * actStride + k0 + kq * 4);
#pragma unroll
            for (int j = 0; j < 4; j++) {
                const ulonglong2 w2 = *(const ulonglong2*)(sW + (kq * 4 + j) * 128 + toc * 4);
#pragma unroll
                for (int i = 0; i < 8; i++) {
                    unsigned long long aa = pack2(a[i][j]);
                    ffma2(acc[i][0], w2.x, aa);
                    ffma2(acc[i][1], w2.y, aa);
                }
            }
        }
    }
#pragma unroll
    for (int i = 0; i < 8; i++) {
        float2 p0 = unpack2(acc[i][0]);
        float2 p1 = unpack2(acc[i][1]);
        *(float4*)(sC + (teg * 8 + i) * CST + toc * 4) = make_float4(p0.x, p0.y, p1.x, p1.y);
    }
}

// ---------- per-row GroupNorm(1 group) over 128 channels, warp per row ----------
__device__ void cta_gn(const float* sC, float* dst, int dstStride,
                       const float* __restrict__ gamma, const float* __restrict__ beta,
                       bool relu, int t) {
    const int warp = t >> 5, lane = t & 31;
    float gg[4], bb[4];
#pragma unroll
    for (int j = 0; j < 4; j++) { gg[j] = gamma[lane + 32 * j]; bb[j] = beta[lane + 32 * j]; }
    for (int e = warp; e < TILE; e += 8) {
        const float* row = sC + e * CST;
        float v[4], s = 0.f, s2 = 0.f;
#pragma unroll
        for (int j = 0; j < 4; j++) {
            v[j] = row[lane + 32 * j];
            s += v[j];
            s2 += v[j] * v[j];
        }
#pragma unroll
        for (int o = 16; o > 0; o >>= 1) {
            s += __shfl_xor_sync(0xffffffffu, s, o);
            s2 += __shfl_xor_sync(0xffffffffu, s2, o);
        }
        float mu = s * (1.f / 128.f);
        float var = s2 * (1.f / 128.f) - mu * mu;
        float rstd = rsqrtf(var + GN_EPS);
#pragma unroll
        for (int j = 0; j < 4; j++) {
            float y = (v[j] - mu) * rstd * gg[j] + bb[j];
            if (relu) y = fmaxf(y, 0.f);
            dst[e * dstStride + lane + 32 * j] = y;
        }
    }
}

// ---------- actor pre: q = relu(gn(actors@qW^T)), a = actors@agtW^T ----------
__global__ void __launch_bounds__(NTH, 1)
pre_kernel(const float* __restrict__ actors_in, const float* __restrict__ qW,
           const float* __restrict__ qg, const float* __restrict__ qb,
           const float* __restrict__ aW, int blk) {
    extern __shared__ float sm[];
    float* sA = sm;
    float* sC = sA + TILE * AST;
    float* sW = sC + TILE * CST;
    const float* cur = blk ? g_actors : actors_in;
    const int t = threadIdx.x;
    const int r0 = blockIdx.x * TILE;
    for (int idx = t; idx < TILE * 32; idx += NTH) {
        int e = idx >> 5, c4 = idx & 31;
        *(float4*)(sA + e * AST + c4 * 4) =
            *(const float4*)(cur + (size_t)(r0 + e) * DD + c4 * 4);
    }
    __syncthreads();
    cta_gemm(qW, DD, sA, AST, sC, sW, t);
    __syncthreads();
    cta_gn(sC, g_q + (size_t)r0 * DD, DD, qg, qb, true, t);
    __syncthreads();
    cta_gemm(aW, DD, sA, AST, sC, sW, t);
    __syncthreads();
    for (int idx = t; idx < TILE * 32; idx += NTH) {
        int e = idx >> 5, c4 = idx & 31;
        *(float4*)(g_a + (size_t)(r0 + e) * DD + c4 * 4) = *(const float4*)(sC + e * CST + c4 * 4);
    }
}

// ---------- fused edge pipeline ----------
__global__ void __launch_bounds__(NTH, 1)
edge_kernel(const float* __restrict__ actor_ctrs, const float* __restrict__ node_ctrs,
            const int* __restrict__ hi, const int* __restrict__ wi,
            const float* __restrict__ nodes,
            const float* __restrict__ d0W, const float* __restrict__ d0b,
            const float* __restrict__ d1W, const float* __restrict__ d1g,
            const float* __restrict__ d1b,
            const float* __restrict__ c0W, const float* __restrict__ c0g,
            const float* __restrict__ c0b, const float* __restrict__ c1W) {
    extern __shared__ float sm[];
    float* sIn = sm;                    // [64][388] : [d | q | c]
    float* sA = sIn + TILE * INST;      // [64][132]
    float* sC = sA + TILE * AST;        // [64][132]
    float* sW = sC + TILE * CST;        // [16][128]
    int* shi = (int*)(sW + 16 * 128);
    int* swi = shi + TILE;
    float* sdx = (float*)(swi + TILE);
    float* sdy = sdx + TILE;

    const int t = threadIdx.x;
    const int e0 = blockIdx.x * TILE;
    if (t < TILE) {
        int h = hi[e0 + t], w = wi[e0 + t];
        shi[t] = h;
        swi[t] = w;
        sdx[t] = actor_ctrs[2 * h] - node_ctrs[2 * w];
        sdy[t] = actor_ctrs[2 * h + 1] - node_ctrs[2 * w + 1];
    }
    __syncthreads();
    // H1 = relu(dist0(dvec))
    for (int idx = t; idx < TILE * DD; idx += NTH) {
        int e = idx >> 7, ch = idx & 127;
        float v = fmaf(d0W[2 * ch], sdx[e], fmaf(d0W[2 * ch + 1], sdy[e], d0b[ch]));
        sA[e * AST + ch] = fmaxf(v, 0.f);
    }
    // gather q[hi] and nodes[wi] into sIn cols [128:384)
    for (int idx = t; idx < TILE * 32; idx += NTH) {
        int e = idx >> 5, c4 = idx & 31;
        *(float4*)(sIn + e * INST + DD + c4 * 4) =
            *(const float4*)(g_q + (size_t)shi[e] * DD + c4 * 4);
        *(float4*)(sIn + e * INST + 2 * DD + c4 * 4) =
            *(const float4*)(nodes + (size_t)swi[e] * DD + c4 * 4);
    }
    __syncthreads();
    cta_gemm(d1W, DD, sA, AST, sC, sW, t);      // H1 @ dist1^T
    __syncthreads();
    cta_gn(sC, sIn, INST, d1g, d1b, true, t);   // -> sIn[:,0:128]
    __syncthreads();
    cta_gemm(c0W, 3 * DD, sIn, INST, sC, sW, t);  // [d,q,c] @ ctx0^T
    __syncthreads();
    cta_gn(sC, sA, AST, c0g, c0b, true, t);
    __syncthreads();
    cta_gemm(c1W, DD, sA, AST, sC, sW, t);      // @ ctx1^T
    __syncthreads();
    // scatter-add into g_a
    for (int idx = t; idx < TILE * DD; idx += NTH) {
        int e = idx >> 7, ch = idx & 127;
        atomicAdd(g_a + (size_t)shi[e] * DD + ch, sC[e * CST + ch]);
    }
}

// ---------- actor post: a=relu(gn(a)); a=gn(a@linW^T); out=relu(a+res) ----------
__global__ void __launch_bounds__(NTH, 1)
post_kernel(const float* __restrict__ actors_in, const float* __restrict__ ng,
            const float* __restrict__ nb, const float* __restrict__ lW,
            const float* __restrict__ lg, const float* __restrict__ lb,
            float* __restrict__ out, int blk) {
    extern __shared__ float sm[];
    float* sA = sm;
    float* sC = sA + TILE * AST;
    float* sW = sC + TILE * CST;
    const float* cur = blk ? g_actors : actors_in;
    float* nxt = blk ? out : g_actors;
    const int t = threadIdx.x;
    const int r0 = blockIdx.x * TILE;
    for (int idx = t; idx < TILE * 32; idx += NTH) {
        int e = idx >> 5, c4 = idx & 31;
        *(float4*)(sC + e * CST + c4 * 4) = *(const float4*)(g_a + (size_t)(r0 + e) * DD + c4 * 4);
    }
    __syncthreads();
    cta_gn(sC, sA, AST, ng, nb, true, t);
    __syncthreads();
    cta_gemm(lW, DD, sA, AST, sC, sW, t);
    __syncthreads();
    cta_gn(sC, sA, AST, lg, lb, false, t);
    __syncthreads();
    for (int idx = t; idx < TILE * 32; idx += NTH) {
        int e = idx >> 5, c4 = idx & 31;
        float4 v = *(const float4*)(sA + e * AST + c4 * 4);
        float4 r = *(const float4*)(cur + (size_t)(r0 + e) * DD + c4 * 4);
        float4 o;
        o.x = fmaxf(v.x + r.x, 0.f);
        o.y = fmaxf(v.y + r.y, 0.f);
        o.z = fmaxf(v.z + r.z, 0.f);
        o.w = fmaxf(v.w + r.w, 0.f);
        *(float4*)(nxt + (size_t)(r0 + e) * DD + c4 * 4) = o;
    }
}

#define SMEM_ACT ((TILE * AST + TILE * CST + 16 * 128) * 4)
#define SMEM_EDGE ((TILE * INST + TILE * AST + TILE * CST + 16 * 128) * 4 + TILE * 4 * 4)

extern "C" void kernel_launch(void* const* d_in, const int* in_sizes, int n_in,
                              void* d_out, int out_size) {
    (void)in_sizes; (void)n_in; (void)out_size;
    const float* actors = (const float*)d_in[0];
    const float* nodes = (const float*)d_in[1];
    const float* actor_ctrs = (const float*)d_in[2];
    const float* node_ctrs = (const float*)d_in[3];
    const int* hi = (const int*)d_in[4];
    const int* wi = (const int*)d_in[5];
    const float* d0W = (const float*)d_in[6];
    const float* d0b = (const float*)d_in[7];
    const float* d1W = (const float*)d_in[8];
    const float* d1g = (const float*)d_in[9];
    const float* d1b = (const float*)d_in[10];
    const float* qW = (const float*)d_in[11];
    const float* qg = (const float*)d_in[12];
    const float* qb = (const float*)d_in[13];
    const float* c0W = (const float*)d_in[14];
    const float* c0g = (const float*)d_in[15];
    const float* c0b = (const float*)d_in[16];
    const float* c1W = (const float*)d_in[17];
    const float* aW = (const float*)d_in[18];
    const float* ng = (const float*)d_in[19];
    const float* nb = (const float*)d_in[20];
    const float* lW = (const float*)d_in[21];
    const float* lg = (const float*)d_in[22];
    const float* lb = (const float*)d_in[23];
    float* out = (float*)d_out;

    cudaFuncSetAttribute(pre_kernel, cudaFuncAttributeMaxDynamicSharedMemorySize, SMEM_ACT);
    cudaFuncSetAttribute(edge_kernel, cudaFuncAttributeMaxDynamicSharedMemorySize, SMEM_EDGE);
    cudaFuncSetAttribute(post_kernel, cudaFuncAttributeMaxDynamicSharedMemorySize, SMEM_ACT);

    for (int blk = 0; blk < 2; blk++) {
        const int off = blk * DD;
        pre_kernel<<<NA / TILE, NTH, SMEM_ACT>>>(actors, qW + blk * DD * DD, qg + off, qb + off,
                                                 aW + blk * DD * DD, blk);
        edge_kernel<<<NE / TILE, NTH, SMEM_EDGE>>>(
            actor_ctrs, node_ctrs, hi, wi, nodes,
            d0W + blk * DD * 2, d0b + off,
            d1W + blk * DD * DD, d1g + off, d1b + off,
            c0W + blk * DD * 3 * DD, c0g + off, c0b + off,
            c1W + blk * DD * DD);
        post_kernel<<<NA / TILE, NTH, SMEM_ACT>>>(actors, ng + off, nb + off, lW + blk * DD * DD,
                                                  lg + off, lb + off, out, blk);
    }
}